// round 3
// baseline (speedup 1.0000x reference)
#include <cuda_runtime.h>

#define EC 64

__device__ __forceinline__ float ex2f(float x) {
    float y; asm("ex2.approx.ftz.f32 %0, %1;" : "=f"(y) : "f"(x)); return y;
}
__device__ __forceinline__ float rcpf(float x) {
    float y; asm("rcp.approx.ftz.f32 %0, %1;" : "=f"(y) : "f"(x)); return y;
}
// sigmoid: 1/(1+2^(-x*log2e)); rel err ~1e-7
__device__ __forceinline__ float sigf(float x) {
    return rcpf(1.0f + ex2f(-1.4426950408889634f * x));
}

// One fused kernel: each block recomputes per-element params into smem
// (cheap, amortized), streams activations with 8 independent LDG.128 per
// loop iteration (2 points/thread x 4-element tile) for high MLP.
__global__ void __launch_bounds__(256, 3) rbf_fused(
    const float* __restrict__ wsp,
    const float4* __restrict__ act,
    const float* __restrict__ dists,
    const float* __restrict__ constants,
    const float* __restrict__ centers,
    const float* __restrict__ radii,
    const float* __restrict__ rotations,
    float4* __restrict__ out,
    float* __restrict__ pen_out,
    int n_pts) {
    __shared__ float4 sp[EC * 3];
    int tid = threadIdx.x;

    // ---- per-block setup: threads 0..63 build packed params in smem ----
    if (tid < EC) {
        int e = tid;
        float rx = fabsf(radii[e * 3 + 0]) + 0.005f;
        float ry = fabsf(radii[e * 3 + 1]) + 0.005f;
        float rz = fabsf(radii[e * 3 + 2]) + 0.005f;
        float d0 = 1.0f / (rx + 1e-8f);
        float d1 = 1.0f / (ry + 1e-8f);
        float d2 = 1.0f / (rz + 1e-8f);

        float a0 = rotations[e * 3 + 0];
        float a1 = rotations[e * 3 + 1];
        float a2 = rotations[e * 3 + 2];
        float cx = cosf(a0), sx = sinf(a0);
        float cy = cosf(a1), sy = sinf(a1);
        float cz = cosf(a2), sz = sinf(a2);

        float R00 = cz * cy, R01 = cz * sy * sx - sz * cx, R02 = cz * sy * cx + sz * sx;
        float R10 = sz * cy, R11 = sz * sy * sx + cz * cx, R12 = sz * sy * cx - cz * sx;
        float R20 = -sy,     R21 = cy * sx,                R22 = cy * cx;

        float c00 = d0 * R00 * R00 + d1 * R01 * R01 + d2 * R02 * R02;
        float c01 = d0 * R00 * R10 + d1 * R01 * R11 + d2 * R02 * R12;
        float c02 = d0 * R00 * R20 + d1 * R01 * R21 + d2 * R02 * R22;
        float c11 = d0 * R10 * R10 + d1 * R11 * R11 + d2 * R12 * R12;
        float c12 = d0 * R10 * R20 + d1 * R11 * R21 + d2 * R12 * R22;
        float c22 = d0 * R20 * R20 + d1 * R21 * R21 + d2 * R22 * R22;

        float ccx = centers[e * 3 + 0];
        float ccy = centers[e * 3 + 1];
        float ccz = centers[e * 3 + 2];
        float cab = fabsf(constants[e]);

        sp[e * 3 + 0] = make_float4(c00, c01, c02, c11);
        sp[e * 3 + 1] = make_float4(c12, c22, ccx, ccy);
        sp[e * 3 + 2] = make_float4(ccz, cab, 0.0f, 0.0f);

        // bbox penalty term, added once (block 0 only; pen_out pre-zeroed by memset)
        if (blockIdx.x == 0) {
            float p = fmaxf(ccx - 0.6f, 0.0f) + fmaxf(ccy - 0.6f, 0.0f) + fmaxf(ccz - 0.6f, 0.0f)
                    + fmaxf(-0.6f - ccx, 0.0f) + fmaxf(-0.6f - ccy, 0.0f) + fmaxf(-0.35f - ccz, 0.0f);
            if (p != 0.0f) atomicAdd(pen_out, p);
        }
    }
    __syncthreads();

    // ---- main: 2 points per thread, e-tile of 4 -> 8 LDG.128 in flight ----
    int n0 = blockIdx.x * 512 + tid;
    int n1 = n0 + 256;
    bool v0 = n0 < n_pts;
    bool v1 = n1 < n_pts;
    int m0 = v0 ? n0 : 0;
    int m1 = v1 ? n1 : 0;

    float x0 = wsp[3 * m0 + 0], y0 = wsp[3 * m0 + 1], z0 = wsp[3 * m0 + 2];
    float x1 = wsp[3 * m1 + 0], y1 = wsp[3 * m1 + 1], z1 = wsp[3 * m1 + 2];
    float nld0 = -1.4426950408889634f * dists[m0];
    float nld1 = -1.4426950408889634f * dists[m1];

    float Ux0 = 0.f, Uy0 = 0.f, Uz0 = 0.f, Uw0 = 0.f, S0 = 0.f, pen0 = 0.f;
    float Ux1 = 0.f, Uy1 = 0.f, Uz1 = 0.f, Uw1 = 0.f, S1 = 0.f, pen1 = 0.f;

    for (int e = 0; e < EC; e += 4) {
        float4 A0[4], A1[4];
        #pragma unroll
        for (int j = 0; j < 4; j++) {
            A0[j] = __ldcs(&act[(size_t)(e + j) * n_pts + m0]);
            A1[j] = __ldcs(&act[(size_t)(e + j) * n_pts + m1]);
        }
        #pragma unroll
        for (int j = 0; j < 4; j++) {
            float4 pa = sp[(e + j) * 3 + 0];
            float4 pb = sp[(e + j) * 3 + 1];
            float4 pc = sp[(e + j) * 3 + 2];

            // point 0
            {
                float dx = x0 - pb.z, dy = y0 - pb.w, dz = z0 - pc.x;
                float t0 = pa.x * dx + pa.y * dy + pa.z * dz;
                float t1 = pa.y * dx + pa.w * dy + pb.x * dz;
                float t2 = pa.z * dx + pb.x * dy + pb.y * dz;
                float q  = dx * t0 + dy * t1 + dz * t2;
                float rbf = pc.y * ex2f(-0.7213475204444817f * q);
                pen0 += fmaxf(rbf - 0.01f, 0.0f);
                S0 += rbf;
                float4 a = A0[j];
                float alpha = 1.0f - ex2f(fmaxf(a.w, 0.0f) * nld0);
                Ux0 += rbf * sigf(a.x);
                Uy0 += rbf * sigf(a.y);
                Uz0 += rbf * sigf(a.z);
                Uw0 += rbf * alpha;
            }
            // point 1
            {
                float dx = x1 - pb.z, dy = y1 - pb.w, dz = z1 - pc.x;
                float t0 = pa.x * dx + pa.y * dy + pa.z * dz;
                float t1 = pa.y * dx + pa.w * dy + pb.x * dz;
                float t2 = pa.z * dx + pb.x * dy + pb.y * dz;
                float q  = dx * t0 + dy * t1 + dz * t2;
                float rbf = pc.y * ex2f(-0.7213475204444817f * q);
                pen1 += fmaxf(rbf - 0.01f, 0.0f);
                S1 += rbf;
                float4 a = A1[j];
                float alpha = 1.0f - ex2f(fmaxf(a.w, 0.0f) * nld1);
                Ux1 += rbf * sigf(a.x);
                Uy1 += rbf * sigf(a.y);
                Uz1 += rbf * sigf(a.z);
                Uw1 += rbf * alpha;
            }
        }
    }

    if (v0) {
        float inv = rcpf(S0 + 1e-6f);
        out[n0] = make_float4(Ux0 * inv, Uy0 * inv, Uz0 * inv, Uw0 * inv);
    }
    if (v1) {
        float inv = rcpf(S1 + 1e-6f);
        out[n1] = make_float4(Ux1 * inv, Uy1 * inv, Uz1 * inv, Uw1 * inv);
    }

    // penalty mean-term reduction
    float pen = (v0 ? pen0 : 0.0f) + (v1 ? pen1 : 0.0f);
    #pragma unroll
    for (int o = 16; o; o >>= 1) pen += __shfl_down_sync(0xffffffffu, pen, o);
    __shared__ float wsum[8];
    if ((tid & 31) == 0) wsum[tid >> 5] = pen;
    __syncthreads();
    if (tid == 0) {
        float s = 0.0f;
        #pragma unroll
        for (int i = 0; i < 8; i++) s += wsum[i];
        atomicAdd(pen_out, s * (0.001f / (float)n_pts));
    }
}

extern "C" void kernel_launch(void* const* d_in, const int* in_sizes, int n_in,
                              void* d_out, int out_size) {
    const float* wsp       = (const float*)d_in[0];
    const float* act       = (const float*)d_in[1];
    const float* dists     = (const float*)d_in[2];
    const float* constants = (const float*)d_in[3];
    const float* centers   = (const float*)d_in[4];
    const float* radii     = (const float*)d_in[5];
    const float* rot       = (const float*)d_in[6];

    int n_pts = in_sizes[0] / 3;
    float* out = (float*)d_out;
    float* pen = out + (out_size - 1);

    cudaMemsetAsync(pen, 0, sizeof(float));

    int blocks = (n_pts + 511) / 512;
    rbf_fused<<<blocks, 256>>>(wsp, (const float4*)act, dists,
                               constants, centers, radii, rot,
                               (float4*)out, pen, n_pts);
}

// round 5
// speedup vs baseline: 1.1113x; 1.1113x over previous
#include <cuda_runtime.h>

#define EC 64

__device__ __forceinline__ float ex2f(float x) {
    float y; asm("ex2.approx.ftz.f32 %0, %1;" : "=f"(y) : "f"(x)); return y;
}
__device__ __forceinline__ float rcpf(float x) {
    float y; asm("rcp.approx.ftz.f32 %0, %1;" : "=f"(y) : "f"(x)); return y;
}
// sigmoid: 1/(1+2^(-x*log2e)); rel err ~1e-7
__device__ __forceinline__ float sigf(float x) {
    return rcpf(1.0f + ex2f(-1.4426950408889634f * x));
}

// 1 point/thread (high occupancy), e-tile of 4 with front-batched LDG.128
// for per-warp MLP. launch_bounds(256,4) caps regs at 64 so 4 CTAs/SM fit.
__global__ void __launch_bounds__(256, 4) rbf_fused(
    const float* __restrict__ wsp,
    const float4* __restrict__ act,
    const float* __restrict__ dists,
    const float* __restrict__ constants,
    const float* __restrict__ centers,
    const float* __restrict__ radii,
    const float* __restrict__ rotations,
    float4* __restrict__ out,
    float* __restrict__ pen_out,
    int n_pts) {
    __shared__ float4 sp[EC * 3];
    int tid = threadIdx.x;

    // ---- per-block setup: threads 0..63 build packed params in smem ----
    if (tid < EC) {
        int e = tid;
        float rx = fabsf(radii[e * 3 + 0]) + 0.005f;
        float ry = fabsf(radii[e * 3 + 1]) + 0.005f;
        float rz = fabsf(radii[e * 3 + 2]) + 0.005f;
        float d0 = 1.0f / (rx + 1e-8f);
        float d1 = 1.0f / (ry + 1e-8f);
        float d2 = 1.0f / (rz + 1e-8f);

        float a0 = rotations[e * 3 + 0];
        float a1 = rotations[e * 3 + 1];
        float a2 = rotations[e * 3 + 2];
        float cx = cosf(a0), sx = sinf(a0);
        float cy = cosf(a1), sy = sinf(a1);
        float cz = cosf(a2), sz = sinf(a2);

        float R00 = cz * cy, R01 = cz * sy * sx - sz * cx, R02 = cz * sy * cx + sz * sx;
        float R10 = sz * cy, R11 = sz * sy * sx + cz * cx, R12 = sz * sy * cx - cz * sx;
        float R20 = -sy,     R21 = cy * sx,                R22 = cy * cx;

        float c00 = d0 * R00 * R00 + d1 * R01 * R01 + d2 * R02 * R02;
        float c01 = d0 * R00 * R10 + d1 * R01 * R11 + d2 * R02 * R12;
        float c02 = d0 * R00 * R20 + d1 * R01 * R21 + d2 * R02 * R22;
        float c11 = d0 * R10 * R10 + d1 * R11 * R11 + d2 * R12 * R12;
        float c12 = d0 * R10 * R20 + d1 * R11 * R21 + d2 * R12 * R22;
        float c22 = d0 * R20 * R20 + d1 * R21 * R21 + d2 * R22 * R22;

        float ccx = centers[e * 3 + 0];
        float ccy = centers[e * 3 + 1];
        float ccz = centers[e * 3 + 2];
        float cab = fabsf(constants[e]);

        sp[e * 3 + 0] = make_float4(c00, c01, c02, c11);
        sp[e * 3 + 1] = make_float4(c12, c22, ccx, ccy);
        sp[e * 3 + 2] = make_float4(ccz, cab, 0.0f, 0.0f);

        // bbox penalty term, added once (block 0 only; pen_out pre-zeroed)
        if (blockIdx.x == 0) {
            float p = fmaxf(ccx - 0.6f, 0.0f) + fmaxf(ccy - 0.6f, 0.0f) + fmaxf(ccz - 0.6f, 0.0f)
                    + fmaxf(-0.6f - ccx, 0.0f) + fmaxf(-0.6f - ccy, 0.0f) + fmaxf(-0.35f - ccz, 0.0f);
            if (p != 0.0f) atomicAdd(pen_out, p);
        }
    }
    __syncthreads();

    int n = blockIdx.x * 256 + tid;
    float pen = 0.0f;

    if (n < n_pts) {
        float x = wsp[3 * n + 0];
        float y = wsp[3 * n + 1];
        float z = wsp[3 * n + 2];
        float negl2d = -1.4426950408889634f * dists[n];

        float Ux = 0.f, Uy = 0.f, Uz = 0.f, Uw = 0.f, S = 0.f;

        for (int e = 0; e < EC; e += 4) {
            // front-batched independent loads -> 4 LDG.128 in flight
            float4 A[4];
            #pragma unroll
            for (int j = 0; j < 4; j++)
                A[j] = act[(size_t)(e + j) * n_pts + n];

            #pragma unroll
            for (int j = 0; j < 4; j++) {
                float4 pa = sp[(e + j) * 3 + 0];
                float4 pb = sp[(e + j) * 3 + 1];
                float4 pc = sp[(e + j) * 3 + 2];

                float dx = x - pb.z, dy = y - pb.w, dz = z - pc.x;
                float t0 = pa.x * dx + pa.y * dy + pa.z * dz;
                float t1 = pa.y * dx + pa.w * dy + pb.x * dz;
                float t2 = pa.z * dx + pb.x * dy + pb.y * dz;
                float q  = dx * t0 + dy * t1 + dz * t2;

                float rbf = pc.y * ex2f(-0.7213475204444817f * q);
                pen += fmaxf(rbf - 0.01f, 0.0f);
                S += rbf;

                float4 a = A[j];
                float alpha = 1.0f - ex2f(fmaxf(a.w, 0.0f) * negl2d);
                Ux += rbf * sigf(a.x);
                Uy += rbf * sigf(a.y);
                Uz += rbf * sigf(a.z);
                Uw += rbf * alpha;
            }
        }

        float inv = rcpf(S + 1e-6f);
        out[n] = make_float4(Ux * inv, Uy * inv, Uz * inv, Uw * inv);
    }

    // penalty mean-term reduction: warp shuffle -> smem -> one atomic per block
    #pragma unroll
    for (int o = 16; o; o >>= 1) pen += __shfl_down_sync(0xffffffffu, pen, o);
    __shared__ float wsum[8];
    if ((tid & 31) == 0) wsum[tid >> 5] = pen;
    __syncthreads();
    if (tid == 0) {
        float s = 0.0f;
        #pragma unroll
        for (int i = 0; i < 8; i++) s += wsum[i];
        atomicAdd(pen_out, s * (0.001f / (float)n_pts));
    }
}

extern "C" void kernel_launch(void* const* d_in, const int* in_sizes, int n_in,
                              void* d_out, int out_size) {
    const float* wsp       = (const float*)d_in[0];
    const float* act       = (const float*)d_in[1];
    const float* dists     = (const float*)d_in[2];
    const float* constants = (const float*)d_in[3];
    const float* centers   = (const float*)d_in[4];
    const float* radii     = (const float*)d_in[5];
    const float* rot       = (const float*)d_in[6];

    int n_pts = in_sizes[0] / 3;
    float* out = (float*)d_out;
    float* pen = out + (out_size - 1);

    cudaMemsetAsync(pen, 0, sizeof(float));

    int blocks = (n_pts + 255) / 256;
    rbf_fused<<<blocks, 256>>>(wsp, (const float4*)act, dists,
                               constants, centers, radii, rot,
                               (float4*)out, pen, n_pts);
}